// round 1
// baseline (speedup 1.0000x reference)
#include <cuda_runtime.h>

// DynamicDownsampling: out[b,c,h,w] = sum_p softmax(kernel[b,:,h,w])[p] * x_padded[b,c,h+di,w+dj]
// x: [4,32,256,256] f32, kernel: [4,25,256,256] f32, edge (replicate) padding, p = di*5+dj.

#define KS   5
#define PAD  2
#define KK   25
#define H    256
#define W    256
#define C    32
#define B    4

#define TW   32           // tile width  (pixels per block, x)
#define TH   16           // tile height (pixels per block, y)
#define HWID (TW + 2*PAD) // 36
#define HHEI (TH + 2*PAD) // 20
#define NTHREADS (TW * TH) // 512

__global__ __launch_bounds__(NTHREADS)
void dds_kernel(const float* __restrict__ x,
                const float* __restrict__ kern,
                float* __restrict__ out)
{
    __shared__ float tile[HHEI][HWID];

    const int tid = threadIdx.x;
    const int tx  = tid & (TW - 1);
    const int ty  = tid >> 5;           // TW == 32

    const int bx = blockIdx.x;          // 0..7
    const int by = blockIdx.y;          // 0..15
    const int b  = blockIdx.z;          // 0..3

    const int gx = bx * TW + tx;
    const int gy = by * TH + ty;

    // ---- per-pixel softmax weights over the 25 kernel planes (channel-invariant) ----
    const float* kp = kern + ((size_t)b * KK) * (H * W) + (size_t)gy * W + gx;
    float e[KK];
    float m = -1e30f;
    #pragma unroll
    for (int p = 0; p < KK; ++p) {
        e[p] = kp[(size_t)p * (H * W)];
        m = fmaxf(m, e[p]);
    }
    float s = 0.f;
    #pragma unroll
    for (int p = 0; p < KK; ++p) {
        e[p] = __expf(e[p] - m);
        s += e[p];
    }
    const float inv_s = 1.0f / s;

    // ---- channel loop: stage x tile (+halo, edge-clamped) in smem, 25-tap weighted sum ----
    const float* xb = x   + (size_t)b * C * H * W;
    float*       ob = out + (size_t)b * C * H * W;
    const int y0 = by * TH - PAD;
    const int x0 = bx * TW - PAD;
    const size_t opix = (size_t)gy * W + gx;

    for (int c = 0; c < C; ++c) {
        const float* xc = xb + (size_t)c * (H * W);

        __syncthreads();   // protect tile reuse from previous channel's readers
        #pragma unroll
        for (int i = tid; i < HHEI * HWID; i += NTHREADS) {
            const int r   = i / HWID;
            const int col = i - r * HWID;
            int yy = y0 + r;   yy = yy < 0 ? 0 : (yy > H - 1 ? H - 1 : yy);
            int xx = x0 + col; xx = xx < 0 ? 0 : (xx > W - 1 ? W - 1 : xx);
            tile[r][col] = xc[(size_t)yy * W + xx];
        }
        __syncthreads();

        float acc = 0.f;
        #pragma unroll
        for (int di = 0; di < KS; ++di) {
            #pragma unroll
            for (int dj = 0; dj < KS; ++dj) {
                acc = fmaf(e[di * KS + dj], tile[ty + di][tx + dj], acc);
            }
        }
        ob[(size_t)c * (H * W) + opix] = acc * inv_s;
    }
}

extern "C" void kernel_launch(void* const* d_in, const int* in_sizes, int n_in,
                              void* d_out, int out_size)
{
    const float* x    = (const float*)d_in[0];   // [4,32,256,256]
    const float* kern = (const float*)d_in[1];   // [4,25,256,256]
    float*       out  = (float*)d_out;           // [4,32,256,256]

    dim3 grid(W / TW, H / TH, B);   // (8, 16, 4) = 512 blocks
    dds_kernel<<<grid, NTHREADS>>>(x, kern, out);
}

// round 2
// speedup vs baseline: 1.4104x; 1.4104x over previous
#include <cuda_runtime.h>
#include <cstdint>

// DynamicDownsampling: out[b,c,h,w] = softmax_p(kernel[b,p,h,w]) . x_edgepad[b,c,h+di-2,w+dj-2]
// x:[4,32,256,256] f32, kernel:[4,25,256,256] f32. Weights channel-invariant.

#define KS   5
#define PAD  2
#define KK   25
#define H    256
#define W    256
#define C    32
#define B    4

#define TW   32
#define TH   16
#define HWID (TW + 2*PAD)        // 36
#define HHEI (TH + 2*PAD)        // 20
#define TILE_ELEMS (HHEI*HWID)   // 720
#define NTHREADS (TW*TH)         // 512

#define NC   4                   // channels per pipeline stage
#define NG   (C/NC)              // 8 stages
#define GROUP_ELEMS (NC*TILE_ELEMS)          // 2880
#define LOADS_PER_THREAD ((GROUP_ELEMS + NTHREADS - 1)/NTHREADS)  // 6 (last partial)

__device__ __forceinline__ uint32_t smem_u32(const void* p) {
    uint32_t a;
    asm("{ .reg .u64 t; cvta.to.shared.u64 t, %1; cvt.u32.u64 %0, t; }" : "=r"(a) : "l"(p));
    return a;
}
__device__ __forceinline__ void cp_async4(uint32_t dst, const float* src) {
    asm volatile("cp.async.ca.shared.global [%0], [%1], 4;\n" :: "r"(dst), "l"(src));
}
__device__ __forceinline__ void cp_commit() {
    asm volatile("cp.async.commit_group;\n");
}
template<int N> __device__ __forceinline__ void cp_wait() {
    asm volatile("cp.async.wait_group %0;\n" :: "n"(N));
}

__global__ __launch_bounds__(NTHREADS)
void dds_kernel(const float* __restrict__ x,
                const float* __restrict__ kern,
                float* __restrict__ out)
{
    __shared__ float tile[2][NC][TILE_ELEMS];   // 23040 B

    const int tid = threadIdx.x;
    const int tx  = tid & (TW - 1);
    const int ty  = tid >> 5;

    const int bx = blockIdx.x, by = blockIdx.y, b = blockIdx.z;
    const int gx = bx * TW + tx;
    const int gy = by * TH + ty;

    const int y0 = by * TH - PAD;
    const int x0 = bx * TW - PAD;

    const float* xb = x   + (size_t)b * C * H * W;
    float*       ob = out + (size_t)b * C * H * W;

    // ---- precompute this thread's staging offsets (same every stage) ----
    int      soff[LOADS_PER_THREAD];   // (nc*HW + clamped pixel) element offset within group
    uint32_t doff[LOADS_PER_THREAD];   // byte offset within one group buffer
    #pragma unroll
    for (int j = 0; j < LOADS_PER_THREAD; ++j) {
        int i = tid + j * NTHREADS;
        if (i < GROUP_ELEMS) {
            int nc  = i / TILE_ELEMS;
            int rem = i - nc * TILE_ELEMS;
            int r   = rem / HWID;
            int col = rem - r * HWID;
            int yy = y0 + r;   yy = yy < 0 ? 0 : (yy > H-1 ? H-1 : yy);
            int xx = x0 + col; xx = xx < 0 ? 0 : (xx > W-1 ? W-1 : xx);
            soff[j] = nc * (H*W) + yy * W + xx;
            doff[j] = (uint32_t)i * 4u;
        } else {
            soff[j] = -1;
            doff[j] = 0;
        }
    }
    const uint32_t sbase = smem_u32(&tile[0][0][0]);
    const uint32_t buf_bytes = (uint32_t)sizeof(float) * GROUP_ELEMS;

    // ---- stage group 0 immediately (overlaps the weight loads below) ----
    {
        const float* src0 = xb;   // group 0: c0 = 0
        #pragma unroll
        for (int j = 0; j < LOADS_PER_THREAD; ++j)
            if (soff[j] >= 0) cp_async4(sbase + doff[j], src0 + soff[j]);
        cp_commit();
    }

    // ---- per-pixel softmax weights (channel-invariant), 1/sum folded in ----
    const float* kp = kern + ((size_t)b * KK) * (H * W) + (size_t)gy * W + gx;
    float e[KK];
    float m = -1e30f;
    #pragma unroll
    for (int p = 0; p < KK; ++p) {
        e[p] = kp[(size_t)p * (H * W)];
        m = fmaxf(m, e[p]);
    }
    float s = 0.f;
    #pragma unroll
    for (int p = 0; p < KK; ++p) { e[p] = __expf(e[p] - m); s += e[p]; }
    const float inv_s = 1.0f / s;
    #pragma unroll
    for (int p = 0; p < KK; ++p) e[p] *= inv_s;

    const size_t opix = (size_t)gy * W + gx;
    const uint32_t lds_row = (uint32_t)((ty * HWID + tx) * 4);

    // ---- pipelined channel-group loop ----
    for (int g = 0; g < NG; ++g) {
        const int buf = g & 1;

        // barrier: everyone done READING buf^1 (group g-1) before we overwrite it
        __syncthreads();

        if (g + 1 < NG) {
            const float* srcn = xb + (size_t)(g + 1) * NC * (H * W);
            const uint32_t db = sbase + (uint32_t)(buf ^ 1) * buf_bytes;
            #pragma unroll
            for (int j = 0; j < LOADS_PER_THREAD; ++j)
                if (soff[j] >= 0) cp_async4(db + doff[j], srcn + soff[j]);
            cp_commit();
            cp_wait<1>();   // group g's copies complete (only g+1 still pending)
        } else {
            cp_wait<0>();   // drain everything
        }
        __syncthreads();    // make all threads' arrivals visible

        // compute 4 channels from buf
        const float* tb = &tile[buf][0][0];
        #pragma unroll
        for (int nc = 0; nc < NC; ++nc) {
            const float* t = tb + nc * TILE_ELEMS;
            float acc = 0.f;
            #pragma unroll
            for (int di = 0; di < KS; ++di) {
                const float* trow = t + (ty + di) * HWID + tx;
                #pragma unroll
                for (int dj = 0; dj < KS; ++dj)
                    acc = fmaf(e[di * KS + dj], trow[dj], acc);
            }
            ob[(size_t)(g * NC + nc) * (H * W) + opix] = acc;
        }
    }
}

extern "C" void kernel_launch(void* const* d_in, const int* in_sizes, int n_in,
                              void* d_out, int out_size)
{
    const float* x    = (const float*)d_in[0];
    const float* kern = (const float*)d_in[1];
    float*       out  = (float*)d_out;

    dim3 grid(W / TW, H / TH, B);   // (8,16,4) = 512 blocks
    dds_kernel<<<grid, NTHREADS>>>(x, kern, out);
}

// round 3
// speedup vs baseline: 1.8179x; 1.2889x over previous
#include <cuda_runtime.h>
#include <cstdint>

// DynamicDownsampling: out[b,c,h,w] = softmax_p(kernel[b,p,h,w]) . x_edgepad[b,c,h+di-2,w+dj-2]
// x:[4,32,256,256] f32, kernel:[4,25,256,256] f32. Weights channel-invariant,
// per-pixel. Each thread computes 2 horizontal pixels (x even) so the 6-wide
// sliding window amortizes smem reads: 15 floats / output instead of 25.

#define KS   5
#define PAD  2
#define KK   25
#define H    256
#define W    256
#define C    32
#define B    4
#define HW   (H*W)

#define TW   32                  // output tile width
#define TH   16                  // output tile height
#define HWID (TW + 2*PAD)        // 36
#define HHEI (TH + 2*PAD)        // 20
#define TILE_ELEMS (HHEI*HWID)   // 720
#define NTX  16                  // x-threads (2 px each)
#define NTHREADS (NTX*TH)        // 256

#define NC   8                   // channels per pipeline stage
#define NG   (C/NC)              // 4 stages

__device__ __forceinline__ uint32_t smem_u32(const void* p) {
    uint32_t a;
    asm("{ .reg .u64 t; cvta.to.shared.u64 t, %1; cvt.u32.u64 %0, t; }" : "=r"(a) : "l"(p));
    return a;
}
__device__ __forceinline__ void cp_async4(uint32_t dst, const float* src) {
    asm volatile("cp.async.ca.shared.global [%0], [%1], 4;\n" :: "r"(dst), "l"(src));
}
__device__ __forceinline__ void cp_commit() {
    asm volatile("cp.async.commit_group;\n");
}
template<int N> __device__ __forceinline__ void cp_wait() {
    asm volatile("cp.async.wait_group %0;\n" :: "n"(N));
}

__global__ __launch_bounds__(NTHREADS, 3)
void dds_kernel(const float* __restrict__ x,
                const float* __restrict__ kern,
                float* __restrict__ out)
{
    __shared__ float tile[2][NC][TILE_ELEMS];   // 46080 B
    __shared__ int   pixoff[TILE_ELEMS];        // clamped gmem pixel offsets

    const int tid = threadIdx.x;
    const int txl = tid & (NTX - 1);     // 0..15 (pixel pair index)
    const int ty  = tid >> 4;            // 0..15

    const int bx = blockIdx.x, by = blockIdx.y, b = blockIdx.z;
    const int gx = bx * TW + 2 * txl;    // even
    const int gy = by * TH + ty;

    const int y0 = by * TH - PAD;
    const int x0 = bx * TW - PAD;

    const float* xb = x   + (size_t)b * C * HW;
    float*       ob = out + (size_t)b * C * HW;

    // ---- clamped source-pixel offset table (once per block) ----
    for (int i = tid; i < TILE_ELEMS; i += NTHREADS) {
        int r   = i / HWID;
        int col = i - r * HWID;
        int yy = y0 + r;   yy = yy < 0 ? 0 : (yy > H-1 ? H-1 : yy);
        int xx = x0 + col; xx = xx < 0 ? 0 : (xx > W-1 ? W-1 : xx);
        pixoff[i] = yy * W + xx;
    }
    __syncthreads();

    const uint32_t sbase     = smem_u32(&tile[0][0][0]);
    const uint32_t buf_bytes = (uint32_t)sizeof(float) * NC * TILE_ELEMS;

    // ---- stage group 0 (overlaps weight loads below) ----
    {
        const float* src = xb;
        #pragma unroll
        for (int nc = 0; nc < NC; ++nc) {
            const float* s = src + nc * HW;
            const uint32_t dbase = sbase + (uint32_t)(nc * TILE_ELEMS) * 4u;
            #pragma unroll
            for (int i = tid; i < TILE_ELEMS; i += NTHREADS)
                cp_async4(dbase + (uint32_t)i * 4u, s + pixoff[i]);
        }
        cp_commit();
    }

    // ---- softmax weights for BOTH pixels of the pair (1/sum folded in) ----
    const float2* kp = (const float2*)(kern + ((size_t)b * KK) * HW + (size_t)gy * W + gx);
    float e0[KK], e1[KK];
    float m0 = -1e30f, m1 = -1e30f;
    #pragma unroll
    for (int p = 0; p < KK; ++p) {
        float2 v = kp[(size_t)p * (HW/2)];
        e0[p] = v.x; e1[p] = v.y;
        m0 = fmaxf(m0, v.x); m1 = fmaxf(m1, v.y);
    }
    float s0 = 0.f, s1 = 0.f;
    #pragma unroll
    for (int p = 0; p < KK; ++p) {
        e0[p] = __expf(e0[p] - m0); s0 += e0[p];
        e1[p] = __expf(e1[p] - m1); s1 += e1[p];
    }
    const float i0 = 1.0f / s0, i1 = 1.0f / s1;
    #pragma unroll
    for (int p = 0; p < KK; ++p) { e0[p] *= i0; e1[p] *= i1; }

    const size_t opix = (size_t)gy * W + gx;
    const int tbase_off = ty * HWID + 2 * txl;   // window base within a channel tile

    // ---- pipelined channel-group loop ----
    for (int g = 0; g < NG; ++g) {
        const int buf = g & 1;

        __syncthreads();   // everyone done reading buf^1 before overwrite

        if (g + 1 < NG) {
            const float* src = xb + (size_t)(g + 1) * NC * HW;
            const uint32_t db = sbase + (uint32_t)(buf ^ 1) * buf_bytes;
            #pragma unroll
            for (int nc = 0; nc < NC; ++nc) {
                const float* s = src + nc * HW;
                const uint32_t dbase = db + (uint32_t)(nc * TILE_ELEMS) * 4u;
                #pragma unroll
                for (int i = tid; i < TILE_ELEMS; i += NTHREADS)
                    cp_async4(dbase + (uint32_t)i * 4u, s + pixoff[i]);
            }
            cp_commit();
            cp_wait<1>();   // group g complete (only g+1 pending)
        } else {
            cp_wait<0>();
        }
        __syncthreads();

        const float* tb = &tile[buf][0][0] + tbase_off;
        #pragma unroll
        for (int nc = 0; nc < NC; ++nc) {
            const float* t = tb + nc * TILE_ELEMS;
            float acc0 = 0.f, acc1 = 0.f;
            #pragma unroll
            for (int di = 0; di < KS; ++di) {
                const float* row = t + di * HWID;
                const float2 p0 = *(const float2*)(row);
                const float2 p1 = *(const float2*)(row + 2);
                const float2 p2 = *(const float2*)(row + 4);
                const float d0 = p0.x, d1 = p0.y, d2 = p1.x,
                            d3 = p1.y, d4 = p2.x, d5 = p2.y;
                const int pb = di * KS;
                acc0 = fmaf(e0[pb+0], d0, acc0);  acc1 = fmaf(e1[pb+0], d1, acc1);
                acc0 = fmaf(e0[pb+1], d1, acc0);  acc1 = fmaf(e1[pb+1], d2, acc1);
                acc0 = fmaf(e0[pb+2], d2, acc0);  acc1 = fmaf(e1[pb+2], d3, acc1);
                acc0 = fmaf(e0[pb+3], d3, acc0);  acc1 = fmaf(e1[pb+3], d4, acc1);
                acc0 = fmaf(e0[pb+4], d4, acc0);  acc1 = fmaf(e1[pb+4], d5, acc1);
            }
            float2 o; o.x = acc0; o.y = acc1;
            *(float2*)(ob + (size_t)(g * NC + nc) * HW + opix) = o;
        }
    }
}

extern "C" void kernel_launch(void* const* d_in, const int* in_sizes, int n_in,
                              void* d_out, int out_size)
{
    const float* x    = (const float*)d_in[0];
    const float* kern = (const float*)d_in[1];
    float*       out  = (float*)d_out;

    dim3 grid(W / TW, H / TH, B);   // (8,16,4) = 512 blocks
    dds_kernel<<<grid, NTHREADS>>>(x, kern, out);
}

// round 4
// speedup vs baseline: 2.2031x; 1.2119x over previous
#include <cuda_runtime.h>
#include <cstdint>

// DynamicDownsampling: out[b,c,h,w] = softmax_p(kernel[b,p,h,w]) . x_edgepad 5x5
// x:[4,32,256,256] f32, kernel:[4,25,256,256] f32. Weights channel-invariant.
// Each thread computes a 2x2 output quad: vertical+horizontal tap reuse
// (36 B smem read / output) and f32x2 packed FMA (half FMA-pipe ops).

#define KS   5
#define PAD  2
#define KK   25
#define H    256
#define W    256
#define C    32
#define B    4
#define HW   (H*W)

#define TDIM 32                   // output tile 32x32
#define ROWS (TDIM + 2*PAD)       // 36 staged rows
#define COLM 40                   // padded smem row width (floats); data in cols 2..37
#define TILE_F (ROWS*COLM)        // 1440 floats / channel
#define TILE_B (TILE_F*4)         // 5760 bytes

#define NTHREADS 256              // 16x16 quads
#define NC   4                    // channels per stage
#define NG   (C/NC)               // 8

#define SLOTS_PER_ROW 12          // 8 x 16B interior + 4 x 4B halo
#define SLOTS (ROWS*SLOTS_PER_ROW)  // 432 per channel

typedef unsigned long long ull;

__device__ __forceinline__ uint32_t smem_u32(const void* p) {
    uint32_t a;
    asm("{ .reg .u64 t; cvta.to.shared.u64 t, %1; cvt.u32.u64 %0, t; }" : "=r"(a) : "l"(p));
    return a;
}
__device__ __forceinline__ void cp_async16(uint32_t dst, const float* src) {
    asm volatile("cp.async.cg.shared.global [%0], [%1], 16;\n" :: "r"(dst), "l"(src));
}
__device__ __forceinline__ void cp_async4(uint32_t dst, const float* src) {
    asm volatile("cp.async.ca.shared.global [%0], [%1], 4;\n" :: "r"(dst), "l"(src));
}
__device__ __forceinline__ void cp_commit() { asm volatile("cp.async.commit_group;\n"); }
template<int N> __device__ __forceinline__ void cp_wait() {
    asm volatile("cp.async.wait_group %0;\n" :: "n"(N));
}
__device__ __forceinline__ ull fma2(ull a, ull b, ull c) {
    ull d;
    asm("fma.rn.f32x2 %0, %1, %2, %3;" : "=l"(d) : "l"(a), "l"(b), "l"(c));
    return d;
}
__device__ __forceinline__ ull pack2(float lo, float hi) {
    ull r;
    asm("mov.b64 %0, {%1, %2};" : "=l"(r) : "f"(lo), "f"(hi));
    return r;
}
__device__ __forceinline__ float lo2(ull v) { float a, b; asm("mov.b64 {%0,%1}, %2;" : "=f"(a), "=f"(b) : "l"(v)); return a; }
__device__ __forceinline__ float hi2(ull v) { float a, b; asm("mov.b64 {%0,%1}, %2;" : "=f"(a), "=f"(b) : "l"(v)); return b; }

__global__ __launch_bounds__(NTHREADS, 2)
void dds_kernel(const float* __restrict__ x,
                const float* __restrict__ kern,
                float* __restrict__ out)
{
    __shared__ float tile[2][NC][TILE_F];   // 46080 B

    const int tid = threadIdx.x;
    const int qx  = tid & 15;     // quad col (2 px)
    const int qy  = tid >> 4;     // quad row (2 px)

    const int bx = blockIdx.x, by = blockIdx.y, b = blockIdx.z;
    const int x0 = bx * TDIM;
    const int y0 = by * TDIM - PAD;

    const float* xb = x   + (size_t)b * C * HW;
    float*       ob = out + (size_t)b * C * HW;

    // ---- per-thread staging slots (2 per channel, same pattern every group) ----
    int      soff[2];  uint32_t doff[2];  bool is16[2];
    const bool v1 = (tid + NTHREADS) < SLOTS;
    #pragma unroll
    for (int j = 0; j < 2; ++j) {
        int s = tid + j * NTHREADS;
        if (s >= SLOTS) s = 0;                       // dummy (predicated off)
        const int r = s / SLOTS_PER_ROW;
        const int k = s - r * SLOTS_PER_ROW;
        int yy = y0 + r; yy = yy < 0 ? 0 : (yy > H-1 ? H-1 : yy);
        if (k < 8) {
            is16[j] = true;
            soff[j] = yy * W + x0 + k * 4;
            doff[j] = (uint32_t)(r * (COLM*4) + 16 + k * 16);
        } else {
            is16[j] = false;
            const int kk2 = k - 8;
            const int scol = (kk2 < 2) ? (2 + kk2) : (36 + kk2 - 2);
            int gxp = x0 + ((kk2 < 2) ? (kk2 - 2) : (32 + kk2 - 2));
            gxp = gxp < 0 ? 0 : (gxp > W-1 ? W-1 : gxp);
            soff[j] = yy * W + gxp;
            doff[j] = (uint32_t)(r * (COLM*4) + scol * 4);
        }
    }

    const uint32_t sbase = smem_u32(&tile[0][0][0]);
    const uint32_t buf_bytes = (uint32_t)(NC * TILE_B);

    // ---- stage group 0 (overlaps weight softmax below) ----
    #pragma unroll
    for (int c = 0; c < NC; ++c) {
        const float* src = xb + (size_t)c * HW;
        const uint32_t db = sbase + (uint32_t)c * TILE_B;
        if (is16[0]) cp_async16(db + doff[0], src + soff[0]);
        else         cp_async4 (db + doff[0], src + soff[0]);
        if (v1) {
            if (is16[1]) cp_async16(db + doff[1], src + soff[1]);
            else         cp_async4 (db + doff[1], src + soff[1]);
        }
    }
    cp_commit();

    // ---- softmax weights for the 2x2 quad, packed (col0,col1) per row ----
    const int gx0 = x0 + 2 * qx;
    const int gy0 = by * TDIM + 2 * qy;
    const float2* kp = (const float2*)(kern + ((size_t)b * KK) * HW + (size_t)gy0 * W + gx0);

    ull wv0[KK], wv1[KK];     // packed raw logits, then packed normalized weights
    float m00 = -1e30f, m01 = -1e30f, m10 = -1e30f, m11 = -1e30f;
    #pragma unroll
    for (int p = 0; p < KK; ++p) {
        float2 a = kp[(size_t)p * (HW/2)];            // row gy0
        float2 c = kp[(size_t)p * (HW/2) + W/2];      // row gy0+1
        wv0[p] = pack2(a.x, a.y);
        wv1[p] = pack2(c.x, c.y);
        m00 = fmaxf(m00, a.x); m01 = fmaxf(m01, a.y);
        m10 = fmaxf(m10, c.x); m11 = fmaxf(m11, c.y);
    }
    float s00 = 0.f, s01 = 0.f, s10 = 0.f, s11 = 0.f;
    #pragma unroll
    for (int p = 0; p < KK; ++p) {
        float a0 = __expf(lo2(wv0[p]) - m00), a1 = __expf(hi2(wv0[p]) - m01);
        float c0 = __expf(lo2(wv1[p]) - m10), c1 = __expf(hi2(wv1[p]) - m11);
        s00 += a0; s01 += a1; s10 += c0; s11 += c1;
        wv0[p] = pack2(a0, a1);
        wv1[p] = pack2(c0, c1);
    }
    const float i00 = 1.f/s00, i01 = 1.f/s01, i10 = 1.f/s10, i11 = 1.f/s11;
    #pragma unroll
    for (int p = 0; p < KK; ++p) {
        wv0[p] = pack2(lo2(wv0[p]) * i00, hi2(wv0[p]) * i01);
        wv1[p] = pack2(lo2(wv1[p]) * i10, hi2(wv1[p]) * i11);
    }

    float* obq = ob + (size_t)gy0 * W + gx0;
    const int qbase = (2*qy) * COLM + (2*qx + 2);   // smem window base (floats)

    // ---- pipelined channel-group loop ----
    for (int g = 0; g < NG; ++g) {
        const int buf = g & 1;

        __syncthreads();   // readers of buf^1 done before overwrite

        if (g + 1 < NG) {
            const float* srcg = xb + (size_t)(g + 1) * NC * HW;
            const uint32_t db0 = sbase + (uint32_t)(buf ^ 1) * buf_bytes;
            #pragma unroll
            for (int c = 0; c < NC; ++c) {
                const float* src = srcg + (size_t)c * HW;
                const uint32_t db = db0 + (uint32_t)c * TILE_B;
                if (is16[0]) cp_async16(db + doff[0], src + soff[0]);
                else         cp_async4 (db + doff[0], src + soff[0]);
                if (v1) {
                    if (is16[1]) cp_async16(db + doff[1], src + soff[1]);
                    else         cp_async4 (db + doff[1], src + soff[1]);
                }
            }
            cp_commit();
            cp_wait<1>();
        } else {
            cp_wait<0>();
        }
        __syncthreads();

        const float* tb = &tile[buf][0][0] + qbase;
        #pragma unroll
        for (int c = 0; c < NC; ++c) {
            const float* t = tb + c * TILE_F;
            ull a0 = 0, a1 = 0;    // packed (col0,col1) accumulators, rows 0/1
            #pragma unroll
            for (int dr = 0; dr < 6; ++dr) {
                const ull* rp = (const ull*)(t + dr * COLM);   // 8B aligned
                const ull L0 = rp[0], L1 = rp[1], L2 = rp[2];  // (d0,d1)(d2,d3)(d4,d5)
                const ull P1 = pack2(hi2(L0), lo2(L1));        // (d1,d2)
                const ull P3 = pack2(hi2(L1), lo2(L2));        // (d3,d4)
                if (dr <= 4) {
                    const int pb = dr * KS;
                    a0 = fma2(wv0[pb+0], L0, a0);
                    a0 = fma2(wv0[pb+1], P1, a0);
                    a0 = fma2(wv0[pb+2], L1, a0);
                    a0 = fma2(wv0[pb+3], P3, a0);
                    a0 = fma2(wv0[pb+4], L2, a0);
                }
                if (dr >= 1) {
                    const int pb = (dr - 1) * KS;
                    a1 = fma2(wv1[pb+0], L0, a1);
                    a1 = fma2(wv1[pb+1], P1, a1);
                    a1 = fma2(wv1[pb+2], L1, a1);
                    a1 = fma2(wv1[pb+3], P3, a1);
                    a1 = fma2(wv1[pb+4], L2, a1);
                }
            }
            float* o = obq + (size_t)(g * NC + c) * HW;
            *(ull*)(o)     = a0;   // float2 store row gy0
            *(ull*)(o + W) = a1;   // float2 store row gy0+1
        }
    }
}

extern "C" void kernel_launch(void* const* d_in, const int* in_sizes, int n_in,
                              void* d_out, int out_size)
{
    const float* x    = (const float*)d_in[0];
    const float* kern = (const float*)d_in[1];
    float*       out  = (float*)d_out;

    dim3 grid(W / TDIM, H / TDIM, B);   // (8,8,4) = 256 blocks
    dds_kernel<<<grid, NTHREADS>>>(x, kern, out);
}

// round 5
// speedup vs baseline: 2.3446x; 1.0643x over previous
#include <cuda_runtime.h>
#include <cstdint>

// DynamicDownsampling: out[b,c,h,w] = softmax_p(kernel[b,p,h,w]) . x_edgepad 5x5
// x:[4,32,256,256] f32, kernel:[4,25,256,256] f32. Weights channel-invariant.
// 2x2 output quad per thread (36B smem/output), f32x2 packed FMA, split
// accumulator chains for ILP, 128-thread blocks for 4 independent pipelines/SM.

#define KS   5
#define PAD  2
#define KK   25
#define H    256
#define W    256
#define C    32
#define B    4
#define HW   (H*W)

#define TDX  32                   // output tile width
#define TDY  16                   // output tile height
#define ROWS (TDY + 2*PAD)        // 20 staged rows
#define COLM 40                   // padded smem row width (floats); data cols 2..37
#define TILE_F (ROWS*COLM)        // 800 floats / channel
#define TILE_B (TILE_F*4)         // 3200 bytes

#define NTHREADS 128              // 16x8 quads
#define NC   4                    // channels per stage
#define NG   (C/NC)               // 8

#define SLOTS_PER_ROW 12          // 8 x 16B interior + 4 x 4B halo
#define SLOTS (ROWS*SLOTS_PER_ROW)  // 240 per channel

typedef unsigned long long ull;

__device__ __forceinline__ uint32_t smem_u32(const void* p) {
    uint32_t a;
    asm("{ .reg .u64 t; cvta.to.shared.u64 t, %1; cvt.u32.u64 %0, t; }" : "=r"(a) : "l"(p));
    return a;
}
__device__ __forceinline__ void cp_async16(uint32_t dst, const float* src) {
    asm volatile("cp.async.cg.shared.global [%0], [%1], 16;\n" :: "r"(dst), "l"(src));
}
__device__ __forceinline__ void cp_async4(uint32_t dst, const float* src) {
    asm volatile("cp.async.ca.shared.global [%0], [%1], 4;\n" :: "r"(dst), "l"(src));
}
__device__ __forceinline__ void cp_commit() { asm volatile("cp.async.commit_group;\n"); }
template<int N> __device__ __forceinline__ void cp_wait() {
    asm volatile("cp.async.wait_group %0;\n" :: "n"(N));
}
__device__ __forceinline__ ull fma2(ull a, ull b, ull c) {
    ull d;
    asm("fma.rn.f32x2 %0, %1, %2, %3;" : "=l"(d) : "l"(a), "l"(b), "l"(c));
    return d;
}
__device__ __forceinline__ ull add2(ull a, ull b) {
    ull d;
    asm("add.rn.f32x2 %0, %1, %2;" : "=l"(d) : "l"(a), "l"(b));
    return d;
}
__device__ __forceinline__ ull pack2(float lo, float hi) {
    ull r;
    asm("mov.b64 %0, {%1, %2};" : "=l"(r) : "f"(lo), "f"(hi));
    return r;
}
__device__ __forceinline__ float lo2(ull v) { float a, b; asm("mov.b64 {%0,%1}, %2;" : "=f"(a), "=f"(b) : "l"(v)); return a; }
__device__ __forceinline__ float hi2(ull v) { float a, b; asm("mov.b64 {%0,%1}, %2;" : "=f"(a), "=f"(b) : "l"(v)); return b; }

__global__ __launch_bounds__(NTHREADS, 4)
void dds_kernel(const float* __restrict__ x,
                const float* __restrict__ kern,
                float* __restrict__ out)
{
    __shared__ float tile[2][NC][TILE_F];   // 25600 B

    const int tid = threadIdx.x;
    const int qx  = tid & 15;     // quad col (2 px)
    const int qy  = tid >> 4;     // quad row (2 px), 0..7

    const int bx = blockIdx.x, by = blockIdx.y, b = blockIdx.z;
    const int x0 = bx * TDX;
    const int y0 = by * TDY - PAD;

    const float* xb = x   + (size_t)b * C * HW;
    float*       ob = out + (size_t)b * C * HW;

    // ---- per-thread staging slots (<=2 per channel, same pattern every group) ----
    int      soff[2];  uint32_t doff[2];  bool is16[2];
    const bool v1 = (tid + NTHREADS) < SLOTS;
    #pragma unroll
    for (int j = 0; j < 2; ++j) {
        int s = tid + j * NTHREADS;
        if (s >= SLOTS) s = 0;                       // dummy (predicated off)
        const int r = s / SLOTS_PER_ROW;
        const int k = s - r * SLOTS_PER_ROW;
        int yy = y0 + r; yy = yy < 0 ? 0 : (yy > H-1 ? H-1 : yy);
        if (k < 8) {
            is16[j] = true;
            soff[j] = yy * W + x0 + k * 4;
            doff[j] = (uint32_t)(r * (COLM*4) + 16 + k * 16);
        } else {
            is16[j] = false;
            const int kk2 = k - 8;
            const int scol = (kk2 < 2) ? (2 + kk2) : (36 + kk2 - 2);
            int gxp = x0 + ((kk2 < 2) ? (kk2 - 2) : (32 + kk2 - 2));
            gxp = gxp < 0 ? 0 : (gxp > W-1 ? W-1 : gxp);
            soff[j] = yy * W + gxp;
            doff[j] = (uint32_t)(r * (COLM*4) + scol * 4);
        }
    }

    const uint32_t sbase = smem_u32(&tile[0][0][0]);
    const uint32_t buf_bytes = (uint32_t)(NC * TILE_B);

    // ---- stage group 0 (overlaps weight softmax below) ----
    #pragma unroll
    for (int c = 0; c < NC; ++c) {
        const float* src = xb + (size_t)c * HW;
        const uint32_t db = sbase + (uint32_t)c * TILE_B;
        if (is16[0]) cp_async16(db + doff[0], src + soff[0]);
        else         cp_async4 (db + doff[0], src + soff[0]);
        if (v1) {
            if (is16[1]) cp_async16(db + doff[1], src + soff[1]);
            else         cp_async4 (db + doff[1], src + soff[1]);
        }
    }
    cp_commit();

    // ---- softmax weights for the 2x2 quad, packed (col0,col1) per kernel tap ----
    const int gx0 = x0 + 2 * qx;
    const int gy0 = by * TDY + 2 * qy;
    const float2* kp = (const float2*)(kern + ((size_t)b * KK) * HW + (size_t)gy0 * W + gx0);

    ull wv0[KK], wv1[KK];
    float m00 = -1e30f, m01 = -1e30f, m10 = -1e30f, m11 = -1e30f;
    #pragma unroll
    for (int p = 0; p < KK; ++p) {
        float2 a = kp[(size_t)p * (HW/2)];            // row gy0
        float2 c = kp[(size_t)p * (HW/2) + W/2];      // row gy0+1
        wv0[p] = pack2(a.x, a.y);
        wv1[p] = pack2(c.x, c.y);
        m00 = fmaxf(m00, a.x); m01 = fmaxf(m01, a.y);
        m10 = fmaxf(m10, c.x); m11 = fmaxf(m11, c.y);
    }
    float s00 = 0.f, s01 = 0.f, s10 = 0.f, s11 = 0.f;
    #pragma unroll
    for (int p = 0; p < KK; ++p) {
        float a0 = __expf(lo2(wv0[p]) - m00), a1 = __expf(hi2(wv0[p]) - m01);
        float c0 = __expf(lo2(wv1[p]) - m10), c1 = __expf(hi2(wv1[p]) - m11);
        s00 += a0; s01 += a1; s10 += c0; s11 += c1;
        wv0[p] = pack2(a0, a1);
        wv1[p] = pack2(c0, c1);
    }
    const float i00 = 1.f/s00, i01 = 1.f/s01, i10 = 1.f/s10, i11 = 1.f/s11;
    #pragma unroll
    for (int p = 0; p < KK; ++p) {
        wv0[p] = pack2(lo2(wv0[p]) * i00, hi2(wv0[p]) * i01);
        wv1[p] = pack2(lo2(wv1[p]) * i10, hi2(wv1[p]) * i11);
    }

    float* obq = ob + (size_t)gy0 * W + gx0;
    const int qbase = (2*qy) * COLM + (2*qx + 2);   // smem window base (floats)

    // ---- pipelined channel-group loop ----
    for (int g = 0; g < NG; ++g) {
        const int buf = g & 1;

        __syncthreads();   // readers of buf^1 done before overwrite

        if (g + 1 < NG) {
            const float* srcg = xb + (size_t)(g + 1) * NC * HW;
            const uint32_t db0 = sbase + (uint32_t)(buf ^ 1) * buf_bytes;
            #pragma unroll
            for (int c = 0; c < NC; ++c) {
                const float* src = srcg + (size_t)c * HW;
                const uint32_t db = db0 + (uint32_t)c * TILE_B;
                if (is16[0]) cp_async16(db + doff[0], src + soff[0]);
                else         cp_async4 (db + doff[0], src + soff[0]);
                if (v1) {
                    if (is16[1]) cp_async16(db + doff[1], src + soff[1]);
                    else         cp_async4 (db + doff[1], src + soff[1]);
                }
            }
            cp_commit();
            cp_wait<1>();
        } else {
            cp_wait<0>();
        }
        __syncthreads();

        const float* tb = &tile[buf][0][0] + qbase;
        #pragma unroll
        for (int c = 0; c < NC; ++c) {
            const float* t = tb + c * TILE_F;
            // split accumulator chains: A/B per output row -> 4 chains, depth ~13
            ull a0A = 0, a0B = 0, a1A = 0, a1B = 0;
            #pragma unroll
            for (int dr = 0; dr < 6; ++dr) {
                const ull* rp = (const ull*)(t + dr * COLM);   // 8B aligned
                const ull L0 = rp[0], L1 = rp[1], L2 = rp[2];  // (d0,d1)(d2,d3)(d4,d5)
                const ull P1 = pack2(hi2(L0), lo2(L1));        // (d1,d2)
                const ull P3 = pack2(hi2(L1), lo2(L2));        // (d3,d4)
                if (dr <= 4) {
                    const int pb = dr * KS;
                    a0A = fma2(wv0[pb+0], L0, a0A);
                    a0B = fma2(wv0[pb+1], P1, a0B);
                    a0A = fma2(wv0[pb+2], L1, a0A);
                    a0B = fma2(wv0[pb+3], P3, a0B);
                    a0A = fma2(wv0[pb+4], L2, a0A);
                }
                if (dr >= 1) {
                    const int pb = (dr - 1) * KS;
                    a1B = fma2(wv1[pb+0], L0, a1B);
                    a1A = fma2(wv1[pb+1], P1, a1A);
                    a1B = fma2(wv1[pb+2], L1, a1B);
                    a1A = fma2(wv1[pb+3], P3, a1A);
                    a1B = fma2(wv1[pb+4], L2, a1B);
                }
            }
            float* o = obq + (size_t)(g * NC + c) * HW;
            *(ull*)(o)     = add2(a0A, a0B);   // float2 store row gy0
            *(ull*)(o + W) = add2(a1A, a1B);   // float2 store row gy0+1
        }
    }
}

extern "C" void kernel_launch(void* const* d_in, const int* in_sizes, int n_in,
                              void* d_out, int out_size)
{
    const float* x    = (const float*)d_in[0];
    const float* kern = (const float*)d_in[1];
    float*       out  = (float*)d_out;

    dim3 grid(W / TDX, H / TDY, B);   // (8,16,4) = 512 blocks
    dds_kernel<<<grid, NTHREADS>>>(x, kern, out);
}